// round 12
// baseline (speedup 1.0000x reference)
#include <cuda_runtime.h>
#include <math.h>

// Problem constants (all shapes fixed by the dataset)
#define HH   768
#define H4   (HH / 4)       // 192 float4 per row
#define TT   512
#define NCC  8
#define NLL  8921
#define NCTT 4096
#define NNN  4

#define RB      32
#define ENC_NRB (NCTT / RB)                 // 128 row-blocks of encoding
#define LW_NRB  ((NLL + RB - 1) / RB)       // 279 row-blocks of label_weights
#define NBLK    (ENC_NRB + LW_NRB)          // 407 total blocks

// Deterministic per-block partials (no atomics on data, every needed slot written each call)
__device__ float4 g_Cpart[ENC_NRB][H4];  // encoding row-block column sums
__device__ float4 g_Gpart[LW_NRB][H4];   // label_weights row-block column sums (pre-boundary part)
__device__ float4 g_Gfix[NCC][H4];       // post-boundary remainder of the straddling block
__device__ int    g_ticket;              // arrival counter (reset by last block each call)

// j-range boundaries: jsplit_c = ceil((512c-1)*8921/4096), jmax_c = ceil(512c*8921/4096)-1
__device__ __host__ __forceinline__ int jsplit_f(int c) {
    return (int)(((512LL * c - 1) * 8921 + 4095) >> 12);
}

// Compile-time tables (verified against jsplit_f): segment c owns Gpart rows [RB_LO[c], RB_HI[c])
__constant__ int c_RB_LO[8] = {0, 35, 70, 105, 140, 175, 210, 244};
__constant__ int c_RB_HI[8] = {35, 70, 105, 140, 175, 210, 244, 279};
__constant__ int c_JS[8]    = {0, 1113, 2229, 3344, 4459, 5574, 6689, 7804};
__constant__ int c_JM[8]    = {0, 1115, 2230, 3345, 4460, 5575, 6690, 7805};

__device__ __forceinline__ float4 f4add(float4 a, float4 b) {
    a.x += b.x; a.y += b.y; a.z += b.z; a.w += b.w; return a;
}
__device__ __forceinline__ float4 f4fma(float4 a, float s, float4 acc) {
    acc.x += a.x * s; acc.y += a.y * s; acc.z += a.z * s; acc.w += a.w * s; return acc;
}

// ONE kernel: stream partials, then the LAST block to arrive does the whole combine
// from L2-hot partials. Deterministic: who combines varies, the arithmetic doesn't.
__global__ void fused_kernel(const float4* __restrict__ enc,
                             const float4* __restrict__ lw,
                             const int*    __restrict__ ids_raw,
                             float4*       __restrict__ out) {
    const int t = threadIdx.x;   // float4 column 0..191

    // ---------- Phase 1: streaming partials (identical math to prior rounds) ----------
    if (blockIdx.x < ENC_NRB) {
        const int rb = blockIdx.x;
        const float4* p = enc + (size_t)rb * RB * H4 + t;
        float4 a = make_float4(0.f, 0.f, 0.f, 0.f);
        float4 b = make_float4(0.f, 0.f, 0.f, 0.f);
#pragma unroll
        for (int r = 0; r < RB; r += 2) {
            a = f4add(a, p[(size_t)r * H4]);
            b = f4add(b, p[(size_t)(r + 1) * H4]);
        }
        g_Cpart[rb][t] = f4add(a, b);
    } else {
        const int rb = blockIdx.x - ENC_NRB;
        const int r0 = rb * RB;
        const int r1 = min(r0 + RB, NLL);
        int seg = 0;
#pragma unroll
        for (int c = 1; c <= 7; c++)
            if (jsplit_f(c) <= r0) seg = c;
        const int nb   = (seg < 7) ? jsplit_f(seg + 1) : NLL;
        const int rmid = min(r1, nb);

        const float4* p = lw + (size_t)r0 * H4 + t;
        float4 a = make_float4(0.f, 0.f, 0.f, 0.f);
        for (int r = r0; r < rmid; r++) { a = f4add(a, *p); p += H4; }
        g_Gpart[rb][t] = a;
        if (nb < r1) {  // block straddles a segment boundary: remainder goes to seg+1
            a = make_float4(0.f, 0.f, 0.f, 0.f);
            for (int r = nb; r < r1; r++) { a = f4add(a, *p); p += H4; }
            g_Gfix[seg + 1][t] = a;
        }
    }

    // ---------- Phase 2: ticket; last block combines ----------
    __threadfence();                                 // publish partials
    __shared__ int s_last;
    if (t == 0) {
        const int v = atomicAdd(&g_ticket, 1);
        s_last = (v == NBLK - 1);
        if (s_last) atomicExch(&g_ticket, 0);        // reset for next graph replay
    }
    __syncthreads();
    if (!s_last) return;
    __threadfence();                                 // acquire others' partials

    // ---------- Phase 3: combine — thread t owns float4 h-column t end-to-end ----------
    // decode note_end_chunk_ids: int32 (JAX default) or genuine int64
    int ids[NNN];
    {
        const int a0 = ids_raw[0], a1 = ids_raw[1], a2 = ids_raw[2], a3 = ids_raw[3];
        const bool ok32 = (a0 >= 0) && (a0 <= a1) && (a1 <= a2) && (a2 <= a3) && (a3 < NCC);
        if (ok32) {
            ids[0] = a0; ids[1] = a1; ids[2] = a2; ids[3] = a3;
        } else {
            const long long* q = (const long long*)ids_raw;
            ids[0] = (int)q[0]; ids[1] = (int)q[1]; ids[2] = (int)q[2]; ids[3] = (int)q[3];
        }
    }

    // note-weight table: W[n][c] = softmax-over-notes weight for positions in chunk c
    float W[NNN][NCC];
#pragma unroll
    for (int c = 0; c < NCC; c++) {
        int cnt = 0;
#pragma unroll
        for (int m = 0; m < NNN; m++) cnt += (ids[m] < c) ? 1 : 0;
        const float inv = (cnt > 0) ? (1.f / (float)cnt) : 0.f;
#pragma unroll
        for (int n = 0; n < NNN; n++)
            W[n][c] = (cnt == 0) ? (1.f / NNN) : ((ids[n] < c) ? inv : 0.f);
    }

    // chunk prefix sums P[c] (sum of encoding rows [0, 512c)); 128 L2-hot loads
    float4 P[NCC + 1];
    P[0] = make_float4(0.f, 0.f, 0.f, 0.f);
#pragma unroll
    for (int c = 0; c < NCC; c++) {
        float4 s0 = make_float4(0.f, 0.f, 0.f, 0.f);
        float4 s1 = make_float4(0.f, 0.f, 0.f, 0.f);
#pragma unroll
        for (int k = 0; k < 16; k += 2) {
            s0 = f4add(s0, g_Cpart[c * 16 + k][t]);
            s1 = f4add(s1, g_Cpart[c * 16 + k + 1][t]);
        }
        P[c + 1] = f4add(P[c], f4add(s0, s1));
    }
    const float4 Ptot = P[NCC];

    // per-note score accumulators
    float4 acc[NNN];
#pragma unroll
    for (int n = 0; n < NNN; n++) acc[n] = make_float4(0.f, 0.f, 0.f, 0.f);

    // segment sums G_c (286 L2-hot loads total) folded straight into the notes
#pragma unroll
    for (int c = 0; c < NCC; c++) {
        const int lo = c_RB_LO[c], hi = c_RB_HI[c];
        float4 a = make_float4(0.f, 0.f, 0.f, 0.f);
        float4 b = make_float4(0.f, 0.f, 0.f, 0.f);
        int rb = lo;
        for (; rb + 1 < hi; rb += 2) {
            a = f4add(a, g_Gpart[rb][t]);
            b = f4add(b, g_Gpart[rb + 1][t]);
        }
        if (rb < hi) a = f4add(a, g_Gpart[rb][t]);
        float4 G = f4add(a, b);
        if (c >= 1) G = f4add(G, g_Gfix[c][t]);

        // D-term: acc[n] += W[n][c] * G * Ptot  (Ptot factor applied at the end via G*Ptot)
        const float4 GP = make_float4(G.x * Ptot.x, G.y * Ptot.y, G.z * Ptot.z, G.w * Ptot.w);
#pragma unroll
        for (int n = 0; n < NNN; n++) acc[n] = f4fma(GP, W[n][c], acc[n]);
    }

    // boundary corrections: acc[n] += dW * (A*P[c] + E*Ptot)   (~20 L2-resident lw loads)
#pragma unroll
    for (int c = 1; c <= 7; c++) {
        const int js = c_JS[c], jm = c_JM[c];
        const float4 A = lw[(size_t)jm * H4 + t];
        float4 E = lw[(size_t)js * H4 + t];
        if (js + 1 < jm) E = f4add(E, lw[(size_t)(js + 1) * H4 + t]);
        const float4 T = make_float4(A.x * P[c].x + E.x * Ptot.x,
                                     A.y * P[c].y + E.y * Ptot.y,
                                     A.z * P[c].z + E.z * Ptot.z,
                                     A.w * P[c].w + E.w * Ptot.w);
#pragma unroll
        for (int n = 0; n < NNN; n++)
            acc[n] = f4fma(T, W[n][c - 1] - W[n][c], acc[n]);
    }

    // sigmoid + store (float4)
#pragma unroll
    for (int n = 0; n < NNN; n++) {
        float4 o;
        o.x = 1.f / (1.f + expf(-acc[n].x));
        o.y = 1.f / (1.f + expf(-acc[n].y));
        o.z = 1.f / (1.f + expf(-acc[n].z));
        o.w = 1.f / (1.f + expf(-acc[n].w));
        out[n * H4 + t] = o;
    }
}

extern "C" void kernel_launch(void* const* d_in, const int* in_sizes, int n_in,
                              void* d_out, int out_size) {
    const float* enc = (const float*)d_in[0];   // encoding (4096, 768) f32 (16B-aligned)
    const float* lw  = (const float*)d_in[2];   // label_weights buffer, viewed (8921, 768) f32
    const int*   ids = (const int*)d_in[3];     // note_end_chunk_ids (4,) int32 or int64
    (void)in_sizes; (void)n_in; (void)out_size; // label_queries (d_in[1]) provably unused

    fused_kernel<<<NBLK, H4>>>((const float4*)enc, (const float4*)lw, ids, (float4*)d_out);
}

// round 13
// speedup vs baseline: 2.4153x; 2.4153x over previous
#include <cuda_runtime.h>
#include <math.h>

// Problem constants (all shapes fixed by the dataset)
#define HH   768
#define H4   (HH / 4)       // 192 float4 per row
#define TT   512
#define NCC  8
#define NLL  8921
#define NCTT 4096
#define NNN  4

#define RB      16
#define ENC_NRB (NCTT / RB)                 // 256 row-blocks of encoding
#define LW_NRB  ((NLL + RB - 1) / RB)       // 558 row-blocks of label_weights

// Deterministic per-block partials (no atomics, every needed slot written each call)
__device__ float4 g_Cpart[ENC_NRB][H4];  // encoding row-block column sums
__device__ float4 g_Gpart[LW_NRB][H4];   // label_weights row-block column sums (pre-boundary part)
__device__ float4 g_Gfix[NCC][H4];       // post-boundary remainder of straddling blocks (c=1,2,4,5,6,7)

// j-range boundaries: jsplit_c = ceil((512c-1)*8921/4096), jmax_c = ceil(512c*8921/4096)-1
__device__ __host__ __forceinline__ int jsplit_f(int c) {
    return (int)(((512LL * c - 1) * 8921 + 4095) >> 12);
}

// Compile-time tables for RB=16 (verified against jsplit_f):
// segment c owns Gpart rows rb in [RB_LO[c], RB_HI[c]); jsplit_3=3344 is 16-aligned -> no Gfix[3]
__constant__ int c_RB_LO[8] = {0, 70, 140, 209, 279, 349, 419, 488};
__constant__ int c_RB_HI[8] = {70, 140, 209, 279, 349, 419, 488, 558};
__constant__ int c_JS[8]    = {0, 1113, 2229, 3344, 4459, 5574, 6689, 7804};
__constant__ int c_JM[8]    = {0, 1115, 2230, 3345, 4460, 5575, 6690, 7805};

__device__ __forceinline__ float4 f4add(float4 a, float4 b) {
    a.x += b.x; a.y += b.y; a.z += b.z; a.w += b.w; return a;
}

// Streaming pass: blockIdx.x < ENC_NRB -> encoding, else label_weights.
// 192 threads: thread t owns float4 column t. All load loops fully unrolled
// (predicated where ragged) for maximum memory-level parallelism.
__global__ void __launch_bounds__(192) sums_kernel(const float4* __restrict__ enc,
                                                   const float4* __restrict__ lw) {
    const int t = threadIdx.x;

    if (blockIdx.x < ENC_NRB) {
        const int rb = blockIdx.x;
        const float4* p = enc + (size_t)rb * RB * H4 + t;
        float4 a = make_float4(0.f, 0.f, 0.f, 0.f);
        float4 b = make_float4(0.f, 0.f, 0.f, 0.f);
#pragma unroll
        for (int r = 0; r < RB; r += 2) {
            a = f4add(a, p[(size_t)r * H4]);
            b = f4add(b, p[(size_t)(r + 1) * H4]);
        }
        g_Cpart[rb][t] = f4add(a, b);
    } else {
        const int rb = blockIdx.x - ENC_NRB;
        const int r0 = rb * RB;
        const int r1 = min(r0 + RB, NLL);          // last block has 9 rows
        int seg = 0;
#pragma unroll
        for (int c = 1; c <= 7; c++)
            if (jsplit_f(c) <= r0) seg = c;
        const int nb   = (seg < 7) ? jsplit_f(seg + 1) : NLL;
        const int rmid = min(r1, nb);

        const float4* p = lw + (size_t)r0 * H4 + t;
        // pre-boundary part: fully unrolled, predicated (16 independent loads)
        float4 a = make_float4(0.f, 0.f, 0.f, 0.f);
        float4 b = make_float4(0.f, 0.f, 0.f, 0.f);
#pragma unroll
        for (int r = 0; r < RB; r += 2) {
            if (r0 + r     < rmid) a = f4add(a, p[(size_t)r * H4]);
            if (r0 + r + 1 < rmid) b = f4add(b, p[(size_t)(r + 1) * H4]);
        }
        g_Gpart[rb][t] = f4add(a, b);
        if (nb < r1) {  // straddle: remainder rows [nb, r1) go to segment seg+1
            a = make_float4(0.f, 0.f, 0.f, 0.f);
#pragma unroll
            for (int r = 0; r < RB; r++) {
                const int rr = r0 + r;
                if (rr >= nb && rr < r1) a = f4add(a, p[(size_t)r * H4]);
            }
            g_Gfix[seg + 1][t] = a;
        }
    }
}

// Reduction + algebra. 24 blocks x 256 threads = 32 h-cols x 8 slices.
// Slice s reduces segment s of g_Gpart (<=70 predicated unrolled loads), chunk s of
// g_Cpart (32 loads), and segment s's boundary rows of lw. Zero runtime routing.
__global__ void combine_kernel(const float* __restrict__ lw,
                               const int* __restrict__ ids_raw,
                               float* __restrict__ out) {
    const int hl    = threadIdx.x & 31;
    const int slice = threadIdx.x >> 5;          // 0..7 == segment / chunk id
    const int h     = blockIdx.x * 32 + hl;
    const float* Gp = (const float*)g_Gpart;     // [LW_NRB][HH]
    const float* Cp = (const float*)g_Cpart;     // [ENC_NRB][HH]
    const float* Gf = (const float*)g_Gfix;      // [NCC][HH]

    // --- segment sum of label_weights partials: <=70 independent predicated loads ---
    const int lo = c_RB_LO[slice];
    const int hi = c_RB_HI[slice];
    float g0 = 0.f, g1 = 0.f, g2 = 0.f, g3 = 0.f;
#pragma unroll
    for (int i = 0; i < 70; i += 4) {
        if (lo + i + 0 < hi) g0 += Gp[(size_t)(lo + i + 0) * HH + h];
        if (lo + i + 1 < hi) g1 += Gp[(size_t)(lo + i + 1) * HH + h];
        if (lo + i + 2 < hi) g2 += Gp[(size_t)(lo + i + 2) * HH + h];
        if (lo + i + 3 < hi) g3 += Gp[(size_t)(lo + i + 3) * HH + h];
    }
    float segG = (g0 + g1) + (g2 + g3);
    if (slice >= 1 && slice != 3) segG += Gf[(size_t)slice * HH + h];  // no straddle at c=3

    // --- chunk sum: slice s owns encoding chunk s = Cpart rows [32s, 32s+32) ---
    float s0 = 0.f, s1 = 0.f;
#pragma unroll
    for (int k = 0; k < 32; k += 2) {
        s0 += Cp[(size_t)(slice * 32 + k)     * HH + h];
        s1 += Cp[(size_t)(slice * 32 + k + 1) * HH + h];
    }
    const float chunkS = s0 + s1;

    // --- boundary rows of lw: A = lw[jmax], E = sum lw[jsplit..jmax-1] (<=2 rows) ---
    float A = 0.f, E = 0.f;
    if (slice >= 1) {
        const int js = c_JS[slice], jm = c_JM[slice];
        A = lw[(size_t)jm * HH + h];
        E = lw[(size_t)js * HH + h];
        if (js + 1 < jm) E += lw[(size_t)(js + 1) * HH + h];
    }

    // --- cross-slice exchange through smem (stride 5: conflict-free) ---
    __shared__ float sm[8][32][5];
    sm[slice][hl][0] = segG;
    sm[slice][hl][1] = chunkS;
    sm[slice][hl][2] = A;
    sm[slice][hl][3] = E;
    __syncthreads();

    if (slice == 0) {
        float G[8], S[8], Av[8], Ev[8];
#pragma unroll
        for (int c = 0; c < 8; c++) {
            G[c]  = sm[c][hl][0];
            S[c]  = sm[c][hl][1];
            Av[c] = sm[c][hl][2];
            Ev[c] = sm[c][hl][3];
        }
        float P[NCC + 1];
        P[0] = 0.f;
#pragma unroll
        for (int c = 0; c < NCC; c++) P[c + 1] = P[c] + S[c];
        const float Ptot = P[NCC];

        // decode note_end_chunk_ids: int32 (JAX default) or genuine int64
        int ids[NNN];
        {
            const int a0 = ids_raw[0], a1 = ids_raw[1], a2 = ids_raw[2], a3 = ids_raw[3];
            const bool ok32 = (a0 >= 0) && (a0 <= a1) && (a1 <= a2) && (a2 <= a3) && (a3 < NCC);
            if (ok32) {
                ids[0] = a0; ids[1] = a1; ids[2] = a2; ids[3] = a3;
            } else {
                const long long* q = (const long long*)ids_raw;
                ids[0] = (int)q[0]; ids[1] = (int)q[1]; ids[2] = (int)q[2]; ids[3] = (int)q[3];
            }
        }

        // note-weight table: W[n][c] = softmax-over-notes weight for positions in chunk c
        float W[NNN][NCC];
#pragma unroll
        for (int c = 0; c < NCC; c++) {
            int cnt = 0;
#pragma unroll
            for (int m = 0; m < NNN; m++) cnt += (ids[m] < c) ? 1 : 0;
            const float inv = (cnt > 0) ? (1.f / (float)cnt) : 0.f;
#pragma unroll
            for (int n = 0; n < NNN; n++)
                W[n][c] = (cnt == 0) ? (1.f / NNN) : ((ids[n] < c) ? inv : 0.f);
        }

        // final: score[n,h] = boundary corrections + Ptot-weighted segment sums
#pragma unroll
        for (int n = 0; n < NNN; n++) {
            float D = 0.f, SP = 0.f;
#pragma unroll
            for (int c = 0; c < NCC; c++) D += W[n][c] * G[c];
#pragma unroll
            for (int c = 1; c <= 7; c++) {
                const float dW = W[n][c - 1] - W[n][c];
                SP += dW * (Av[c] * P[c] + Ev[c] * Ptot);
            }
            const float s = SP + Ptot * D;
            out[n * HH + h] = 1.f / (1.f + expf(-s));
        }
    }
}

extern "C" void kernel_launch(void* const* d_in, const int* in_sizes, int n_in,
                              void* d_out, int out_size) {
    const float* enc = (const float*)d_in[0];   // encoding (4096, 768) f32 (16B-aligned)
    const float* lw  = (const float*)d_in[2];   // label_weights buffer, viewed (8921, 768) f32
    const int*   ids = (const int*)d_in[3];     // note_end_chunk_ids (4,) int32 or int64
    float* out = (float*)d_out;                 // (4, 768) f32
    (void)in_sizes; (void)n_in; (void)out_size; // label_queries (d_in[1]) provably unused

    sums_kernel<<<ENC_NRB + LW_NRB, H4>>>((const float4*)enc, (const float4*)lw);
    combine_kernel<<<24, 256>>>(lw, ids, out);
}